// round 13
// baseline (speedup 1.0000x reference)
#include <cuda_runtime.h>
#include <cuda_bf16.h>
#include <cstdint>
#include <math.h>

// Problem: hidden_states (64, 577, 1024) fp32 -> out (64, 289, 1024) fp32
#define Bn   64
#define Tn   577
#define Cn   1024
#define NE   288      // even tokens (2,4,...,576) that merge into odds
#define NO   288      // odd tokens (1,3,...,575) = merge destinations
#define TOUT 289
#define CAP  16       // candidate slots per row (overflow -> exact full scan)

// ---- static device scratch (no runtime allocation allowed) ----
__device__ float g_rnormO[Bn * NO];
__device__ int   g_ccnt  [Bn * NE];
__device__ int   g_cand  [Bn * NE * CAP];
__device__ int   g_dst   [Bn * NE];
__device__ int   g_off   [Bn * NO];
__device__ int   g_cnt   [Bn * NO];
__device__ int   g_list  [Bn * NE];

// ---------------- helpers ----------------
__device__ __forceinline__ uint32_t smem_u32(const void* p) {
    uint32_t a;
    asm("{ .reg .u64 t; cvta.to.shared.u64 t, %1; cvt.u32.u64 %0, t; }" : "=r"(a) : "l"(p));
    return a;
}
__device__ __forceinline__ void ldm_x4(uint32_t* r, uint32_t addr) {
    asm volatile("ldmatrix.sync.aligned.m8n8.x4.shared.b16 {%0,%1,%2,%3}, [%4];"
        : "=r"(r[0]), "=r"(r[1]), "=r"(r[2]), "=r"(r[3]) : "r"(addr));
}
__device__ __forceinline__ void ldm_x2(uint32_t* r, uint32_t addr) {
    asm volatile("ldmatrix.sync.aligned.m8n8.x2.shared.b16 {%0,%1}, [%2];"
        : "=r"(r[0]), "=r"(r[1]) : "r"(addr));
}
__device__ __forceinline__ void mma_bf16(float* c, const uint32_t* a, const uint32_t* bfr) {
    asm volatile("mma.sync.aligned.m16n8k16.row.col.f32.bf16.bf16.f32 "
        "{%0,%1,%2,%3}, {%4,%5,%6,%7}, {%8,%9}, {%0,%1,%2,%3};"
        : "+f"(c[0]), "+f"(c[1]), "+f"(c[2]), "+f"(c[3])
        : "r"(a[0]), "r"(a[1]), "r"(a[2]), "r"(a[3]), "r"(bfr[0]), "r"(bfr[1]));
}
__device__ __forceinline__ uint32_t pk(float x, float y) {
    __nv_bfloat162 h = __floats2bfloat162_rn(x, y);
    return *(uint32_t*)&h;
}

// ---------------- K1: 96x288 strip GEMM + fused norms + candidate filter ----------------
// Block (it, b): scores for 96 even rows x ALL 288 odd cols live in registers.
// B loaded whole per block -> rnorm computed locally (identical fixed order in every
// block -> bitwise identical); epilogue does normalize + row-max + window + candidate
// lists entirely on-chip. g_scores is never materialized.
#define KC   64
#define SMA_OFF  0            // sA: 96 x 72 bf16 = 13824 B
#define SMB_OFF  13824        // sB: 288 x 72 bf16 = 41472 B
#define SRN_OFF  55296        // s_rn: 288 f
#define SAN_OFF  56448        // s_an: 96 f
#define SRED_OFF 56832        // s_red: 96 x 4 f
#define SCNT_OFF 58368        // s_cnt: 96 i
#define SCAND_OFF 58752       // s_cand: 96 x CAP i
#define DYN_SMEM  (SCAND_OFF + 96 * CAP * 4)

__global__ __launch_bounds__(256) void k_gemm_fused(const float* __restrict__ X) {
    extern __shared__ __align__(16) char dsm[];
    __nv_bfloat16* sA = (__nv_bfloat16*)(dsm + SMA_OFF);
    __nv_bfloat16* sB = (__nv_bfloat16*)(dsm + SMB_OFF);
    float* s_rn  = (float*)(dsm + SRN_OFF);
    float* s_an  = (float*)(dsm + SAN_OFF);
    float* s_red = (float*)(dsm + SRED_OFF);
    int*   s_cnt = (int*)(dsm + SCNT_OFF);
    int*   s_cand= (int*)(dsm + SCAND_OFF);

    const int b = blockIdx.y, it = blockIdx.x;
    const int tid = threadIdx.x, wid = tid >> 5, lane = tid & 31;
    const int wm = wid >> 2, wn = wid & 3;           // warp grid 2(M) x 4(N)
    const float* Xb = X + (size_t)b * Tn * Cn;

    // Global-load jobs: A 96x8=768 (3/thread), B 288x8=2304 (9/thread)
    int rowA[3]; uint32_t offA[3];
    #pragma unroll
    for (int u = 0; u < 3; u++) {
        const int v = tid + u * 256; rowA[u] = v >> 3;
        offA[u] = (uint32_t)(2 * (it * 96 + rowA[u] + 1)) * Cn + (v & 7) * 8;
    }
    int rowB[9]; uint32_t offB[9];
    #pragma unroll
    for (int u = 0; u < 9; u++) {
        const int v = tid + u * 256; rowB[u] = v >> 3;
        offB[u] = (uint32_t)(2 * rowB[u] + 1) * Cn + (v & 7) * 8;
    }

    const uint32_t base = smem_u32(dsm);
    uint32_t aAddr[3];
    #pragma unroll
    for (int s = 0; s < 3; s++)
        aAddr[s] = base + SMA_OFF + (((wm * 48 + s * 16 + (lane & 15)) * 72 + (lane >> 4) * 8) << 1);
    uint32_t bAddr[9];
    #pragma unroll
    for (int p = 0; p < 9; p++)
        bAddr[p] = base + SMB_OFF + (((wn * 72 + p * 8 + (lane & 7)) * 72 + ((lane >> 3) & 1) * 8) << 1);

    float acc[3][9][4];
    #pragma unroll
    for (int s = 0; s < 3; s++)
        #pragma unroll
        for (int p = 0; p < 9; p++)
            #pragma unroll
            for (int e = 0; e < 4; e++) acc[s][p][e] = 0.f;

    float sqa[3] = {0.f, 0.f, 0.f};
    float sqb[9] = {0.f, 0.f, 0.f, 0.f, 0.f, 0.f, 0.f, 0.f, 0.f};

    #pragma unroll 1
    for (int kt = 0; kt < Cn / KC; kt++) {
        const int k0 = kt * KC;
        __syncthreads();                 // previous compute done reading smem
        #pragma unroll
        for (int u = 0; u < 3; u++) {
            const float4 x0 = *(const float4*)(Xb + offA[u] + k0);
            const float4 x1 = *(const float4*)(Xb + offA[u] + k0 + 4);
            uint4 v;
            v.x = pk(x0.x, x0.y); v.y = pk(x0.z, x0.w);
            v.z = pk(x1.x, x1.y); v.w = pk(x1.z, x1.w);
            const int vIdx = tid + u * 256;
            *(uint4*)(sA + (vIdx >> 3) * 72 + (vIdx & 7) * 8) = v;
            sqa[u] += x0.x*x0.x + x0.y*x0.y + x0.z*x0.z + x0.w*x0.w
                    + x1.x*x1.x + x1.y*x1.y + x1.z*x1.z + x1.w*x1.w;
        }
        #pragma unroll
        for (int u = 0; u < 9; u++) {
            const float4 x0 = *(const float4*)(Xb + offB[u] + k0);
            const float4 x1 = *(const float4*)(Xb + offB[u] + k0 + 4);
            uint4 v;
            v.x = pk(x0.x, x0.y); v.y = pk(x0.z, x0.w);
            v.z = pk(x1.x, x1.y); v.w = pk(x1.z, x1.w);
            const int vIdx = tid + u * 256;
            *(uint4*)(sB + (vIdx >> 3) * 72 + (vIdx & 7) * 8) = v;
            sqb[u] += x0.x*x0.x + x0.y*x0.y + x0.z*x0.z + x0.w*x0.w
                    + x1.x*x1.x + x1.y*x1.y + x1.z*x1.z + x1.w*x1.w;
        }
        __syncthreads();
        #pragma unroll
        for (int step = 0; step < KC / 16; step++) {
            uint32_t aF[3][4], bF[9][2];
            #pragma unroll
            for (int s = 0; s < 3; s++) ldm_x4(aF[s], aAddr[s] + step * 32);
            #pragma unroll
            for (int p = 0; p < 9; p++) ldm_x2(bF[p], bAddr[p] + step * 32);
            #pragma unroll
            for (int s = 0; s < 3; s++)
                #pragma unroll
                for (int p = 0; p < 9; p++) mma_bf16(acc[s][p], aF[s], bF[p]);
        }
    }
    __syncthreads();

    // ---- norms: 8-lane shfl tree (jobs map 8 consecutive threads per row) ----
    #pragma unroll
    for (int u = 0; u < 9; u++) {
        float s = sqb[u];
        #pragma unroll
        for (int o = 1; o < 8; o <<= 1) s += __shfl_xor_sync(0xffffffffu, s, o);
        if ((tid & 7) == 0) s_rn[rowB[u]] = 1.0f / sqrtf(s);
    }
    #pragma unroll
    for (int u = 0; u < 3; u++) {
        float s = sqa[u];
        #pragma unroll
        for (int o = 1; o < 8; o <<= 1) s += __shfl_xor_sync(0xffffffffu, s, o);
        if ((tid & 7) == 0) s_an[rowA[u]] = sqrtf(s);
    }
    if (tid < 96) s_cnt[tid] = 0;
    __syncthreads();

    // ---- normalize accs + per-row max partials ----
    const int tr = lane >> 2, tc = (lane & 3) * 2;
    float2 rr[9];
    #pragma unroll
    for (int p = 0; p < 9; p++) rr[p] = *(float2*)&s_rn[wn * 72 + p * 8 + tc];
    #pragma unroll
    for (int s = 0; s < 3; s++) {
        #pragma unroll
        for (int p = 0; p < 9; p++) {
            acc[s][p][0] *= rr[p].x; acc[s][p][1] *= rr[p].y;
            acc[s][p][2] *= rr[p].x; acc[s][p][3] *= rr[p].y;
        }
        #pragma unroll
        for (int h = 0; h < 2; h++) {
            float m = -3.0e38f;
            #pragma unroll
            for (int p = 0; p < 9; p++) m = fmaxf(m, fmaxf(acc[s][p][2*h], acc[s][p][2*h+1]));
            m = fmaxf(m, __shfl_xor_sync(0xffffffffu, m, 1));
            m = fmaxf(m, __shfl_xor_sync(0xffffffffu, m, 2));
            if ((lane & 3) == 0) s_red[(wm * 48 + s * 16 + tr + h * 8) * 4 + wn] = m;
        }
    }
    __syncthreads();

    // ---- candidate collection (window [max - 2B, max], B = 0.006*|a_i|) ----
    // List order is nondeterministic (shared atomics) but the exact pass uses an
    // explicit (v, j) tie-break, so the final dst is order-invariant.
    #pragma unroll
    for (int s = 0; s < 3; s++) {
        #pragma unroll
        for (int h = 0; h < 2; h++) {
            const int row = wm * 48 + s * 16 + tr + h * 8;
            const float gm = fmaxf(fmaxf(s_red[row * 4 + 0], s_red[row * 4 + 1]),
                                   fmaxf(s_red[row * 4 + 2], s_red[row * 4 + 3]));
            const float thr = gm - 0.012f * s_an[row];
            #pragma unroll
            for (int p = 0; p < 9; p++) {
                #pragma unroll
                for (int e = 0; e < 2; e++) {
                    const float v = acc[s][p][2*h + e];
                    if (v >= thr) {
                        const int col = wn * 72 + p * 8 + tc + e;
                        const int slot = atomicAdd(&s_cnt[row], 1);
                        if (slot < CAP) s_cand[row * CAP + slot] = col;
                    }
                }
            }
        }
    }
    __syncthreads();

    // ---- write candidates + counts (+ rnorm once) ----
    const int ib = b * NE + it * 96;
    if (tid < 96) g_ccnt[ib + tid] = s_cnt[tid];
    for (int idx = tid; idx < 96 * CAP; idx += 256)
        g_cand[(size_t)ib * CAP + idx] = s_cand[idx];
    if (it == 0)
        for (int j = tid; j < NO; j += 256) g_rnormO[b * NO + j] = s_rn[j];
}

// ---------------- K2: exact fp32 verify of candidates ----------------
__device__ __forceinline__ float exact_score(const float4 a[8], const float* __restrict__ pb,
                                             int lane, float rn) {
    float s = 0.f;
    #pragma unroll
    for (int q = 0; q < 8; q++) {
        const float4 v = *(const float4*)(pb + q * 128 + lane * 4);
        s += a[q].x * v.x + a[q].y * v.y + a[q].z * v.z + a[q].w * v.w;
    }
    #pragma unroll
    for (int o = 16; o > 0; o >>= 1) s += __shfl_xor_sync(0xffffffffu, s, o);
    return s * rn;
}

__global__ __launch_bounds__(256) void k_exact(const float* __restrict__ X) {
    const int w = threadIdx.x >> 5, lane = threadIdx.x & 31;
    const int b = blockIdx.x / 36, sub = blockIdx.x % 36;   // group by b -> L2 reuse
    const int i = sub * 8 + w;
    const int id = b * NE + i;

    const int cnt = g_ccnt[id];
    if (cnt == 1) {               // proven unique by the error bound — no verification
        if (lane == 0) g_dst[id] = g_cand[(size_t)id * CAP];
        return;
    }

    const float* Xb = X + (size_t)b * Tn * Cn;
    float4 a[8];
    const float* pa = Xb + (size_t)(2 * i + 2) * Cn;
    #pragma unroll
    for (int q = 0; q < 8; q++) a[q] = *(const float4*)(pa + q * 128 + lane * 4);

    float best = -3.0e38f; int bj = NO;
    if (cnt <= CAP) {
        for (int s = 0; s < cnt; s++) {
            const int j = g_cand[(size_t)id * CAP + s];
            const float v = exact_score(a, Xb + (size_t)(2 * j + 1) * Cn, lane, g_rnormO[b * NO + j]);
            if (v > best || (v == best && j < bj)) { best = v; bj = j; }
        }
    } else {                      // overflow: deterministic full scan (rare)
        for (int j = 0; j < NO; j++) {
            const float v = exact_score(a, Xb + (size_t)(2 * j + 1) * Cn, lane, g_rnormO[b * NO + j]);
            if (v > best || (v == best && j < bj)) { best = v; bj = j; }
        }
    }
    if (lane == 0) g_dst[id] = bj;
}

// ---------------- K3: deterministic CSR build (parallel prefix, no atomics) ----------------
__global__ __launch_bounds__(288) void k_build_csr() {
    __shared__ int s_dst[NE];
    __shared__ int s_ws[9];
    const int b = blockIdx.x, t = threadIdx.x, wid = t >> 5, lane = t & 31;
    s_dst[t] = g_dst[b * NE + t];
    __syncthreads();

    int c = 0;
    #pragma unroll 4
    for (int i = 0; i < NE; i++) c += (s_dst[i] == t);

    int inc = c;
    #pragma unroll
    for (int o = 1; o < 32; o <<= 1) {
        const int v = __shfl_up_sync(0xffffffffu, inc, o);
        if (lane >= o) inc += v;
    }
    if (lane == 31) s_ws[wid] = inc;
    __syncthreads();
    int wo = 0;
    #pragma unroll
    for (int wv = 0; wv < 9; wv++) wo += (wv < wid) ? s_ws[wv] : 0;
    const int off = wo + inc - c;   // exclusive prefix

    int wv = 0;
    for (int i = 0; i < NE; i++)
        if (s_dst[i] == t) g_list[b * NE + off + (wv++)] = i;   // ascending i
    g_off[b * NO + t] = off;
    g_cnt[b * NO + t] = c;
}

// ---------------- K4: merge via CSR gather ----------------
__global__ __launch_bounds__(256) void k_merge(const float* __restrict__ X, float* __restrict__ out) {
    __shared__ int s_idx[NE];
    const int b = blockIdx.y, row = blockIdx.x, t = threadIdx.x;
    float* orow = out + ((size_t)b * TOUT + row) * Cn;
    const float* Xb = X + (size_t)b * Tn * Cn;

    if (row == 0) {   // lone unm token = original token 0
        *(float4*)(orow + t * 4) = *(const float4*)(Xb + t * 4);
        return;
    }
    const int j   = row - 1;
    const int off = g_off[b * NO + j];
    const int cnt = g_cnt[b * NO + j];

    for (int s = t; s < cnt; s += 256) s_idx[s] = g_list[b * NE + off + s];
    __syncthreads();

    float4 a = *(const float4*)(Xb + (size_t)(2 * j + 1) * Cn + t * 4);
    if (cnt > 0) {
        float4 nxt = *(const float4*)(Xb + (size_t)(2 * (s_idx[0] + 1)) * Cn + t * 4);
        for (int s = 0; s < cnt; s++) {
            const float4 cur = nxt;
            if (s + 1 < cnt)
                nxt = *(const float4*)(Xb + (size_t)(2 * (s_idx[s + 1] + 1)) * Cn + t * 4);
            a.x += cur.x; a.y += cur.y; a.z += cur.z; a.w += cur.w;
        }
    }
    const float inv = 1.0f / (float)(cnt + 1);
    a.x *= inv; a.y *= inv; a.z *= inv; a.w *= inv;
    *(float4*)(orow + t * 4) = a;
}

// ---------------- launch (single stream, reverted from R12 pipeline) ----------------
extern "C" void kernel_launch(void* const* d_in, const int* in_sizes, int n_in,
                              void* d_out, int out_size) {
    const float* X = (const float*)d_in[0];
    float* out = (float*)d_out;

    cudaFuncSetAttribute(k_gemm_fused, cudaFuncAttributeMaxDynamicSharedMemorySize, DYN_SMEM);

    k_gemm_fused<<<dim3(3, Bn), 256, DYN_SMEM>>>(X);
    k_exact     <<<Bn * 36, 256>>>(X);
    k_build_csr <<<Bn, 288>>>();
    k_merge     <<<dim3(TOUT, Bn), 256>>>(X, out);
}

// round 14
// speedup vs baseline: 1.5886x; 1.5886x over previous
#include <cuda_runtime.h>
#include <cuda_bf16.h>
#include <cstdint>
#include <math.h>

// Problem: hidden_states (64, 577, 1024) fp32 -> out (64, 289, 1024) fp32
#define Bn   64
#define Tn   577
#define Cn   1024
#define NE   288      // even tokens (2,4,...,576) that merge into odds
#define NO   288      // odd tokens (1,3,...,575) = merge destinations
#define TOUT 289
#define BCHUNK 32     // batches per pipeline chunk (2 chunks)

// ---- static device scratch (no runtime allocation allowed) ----
__device__ float g_anorm [Bn * NE];
__device__ float g_rnormO[Bn * NO];
__device__ float g_scores[(size_t)Bn * NE * NO];  // raw bf16-dot scores [b][i][j]
__device__ int   g_dst   [Bn * NE];
__device__ int   g_off   [Bn * NO];
__device__ int   g_cnt   [Bn * NO];
__device__ int   g_list  [Bn * NE];

// ---------------- helpers ----------------
__device__ __forceinline__ uint32_t smem_u32(const void* p) {
    uint32_t a;
    asm("{ .reg .u64 t; cvta.to.shared.u64 t, %1; cvt.u32.u64 %0, t; }" : "=r"(a) : "l"(p));
    return a;
}
__device__ __forceinline__ void ldm_x4(uint32_t* r, uint32_t addr) {
    asm volatile("ldmatrix.sync.aligned.m8n8.x4.shared.b16 {%0,%1,%2,%3}, [%4];"
        : "=r"(r[0]), "=r"(r[1]), "=r"(r[2]), "=r"(r[3]) : "r"(addr));
}
__device__ __forceinline__ void ldm_x2(uint32_t* r, uint32_t addr) {
    asm volatile("ldmatrix.sync.aligned.m8n8.x2.shared.b16 {%0,%1}, [%2];"
        : "=r"(r[0]), "=r"(r[1]) : "r"(addr));
}
__device__ __forceinline__ void mma_bf16(float* c, const uint32_t* a, const uint32_t* bfr) {
    asm volatile("mma.sync.aligned.m16n8k16.row.col.f32.bf16.bf16.f32 "
        "{%0,%1,%2,%3}, {%4,%5,%6,%7}, {%8,%9}, {%0,%1,%2,%3};"
        : "+f"(c[0]), "+f"(c[1]), "+f"(c[2]), "+f"(c[3])
        : "r"(a[0]), "r"(a[1]), "r"(a[2]), "r"(a[3]), "r"(bfr[0]), "r"(bfr[1]));
}
__device__ __forceinline__ uint32_t pk(float x, float y) {
    __nv_bfloat162 h = __floats2bfloat162_rn(x, y);
    return *(uint32_t*)&h;
}

// ---------------- K1: fused fp32->bf16 GEMM + norms (R10 body + b0 offset) ----------------
// Block (jt, it, b): D[96 x 96] = bf16(A) @ bf16(B)^T, fp32 accum. K in 16 chunks of 64.
// Edge blocks (jt==0 / it==0) accumulate norms in a fixed deterministic order.
#define KC   64
#define LDS_STRIDE 72
__global__ __launch_bounds__(256) void k_gemm(const float* __restrict__ X, int b0) {
    __shared__ __align__(16) __nv_bfloat16 sA[96 * LDS_STRIDE];
    __shared__ __align__(16) __nv_bfloat16 sB[96 * LDS_STRIDE];

    const int b = blockIdx.z + b0, it = blockIdx.y, jt = blockIdx.x;
    const int tid = threadIdx.x, wid = tid >> 5, lane = tid & 31;
    const int wm = wid >> 2, wn = wid & 3;           // warp grid 2 x 4

    int rowL[3], segL[3];
    #pragma unroll
    for (int u = 0; u < 3; u++) { const int v = tid + u * 256; rowL[u] = v >> 3; segL[u] = v & 7; }

    const float* Arow[3]; const float* Brow[3];
    #pragma unroll
    for (int u = 0; u < 3; u++) {
        Arow[u] = X + ((size_t)b * Tn + 2 * (it * 96 + rowL[u] + 1)) * Cn + segL[u] * 8;  // even token
        Brow[u] = X + ((size_t)b * Tn + 2 * (jt * 96 + rowL[u]) + 1) * Cn + segL[u] * 8;  // odd token
    }

    const uint32_t aBase = smem_u32(sA);
    const uint32_t bBase = smem_u32(sB);
    uint32_t aAddr[3], bAddr[3];
    #pragma unroll
    for (int s = 0; s < 3; s++)
        aAddr[s] = aBase + (((wm * 48 + s * 16 + (lane & 15)) * LDS_STRIDE + (lane >> 4) * 8) << 1);
    #pragma unroll
    for (int p = 0; p < 3; p++)
        bAddr[p] = bBase + (((wn * 24 + p * 8 + (lane & 7)) * LDS_STRIDE + ((lane >> 3) & 1) * 8) << 1);

    float acc[3][3][4];
    #pragma unroll
    for (int s = 0; s < 3; s++)
        #pragma unroll
        for (int p = 0; p < 3; p++)
            #pragma unroll
            for (int e = 0; e < 4; e++) acc[s][p][e] = 0.f;

    float sqa[3] = {0.f, 0.f, 0.f}, sqb[3] = {0.f, 0.f, 0.f};
    const bool doA = (jt == 0), doB = (it == 0);

    float4 pa0[3], pa1[3], pb0[3], pb1[3];
    #pragma unroll
    for (int u = 0; u < 3; u++) {
        pa0[u] = *(const float4*)(Arow[u]);     pa1[u] = *(const float4*)(Arow[u] + 4);
        pb0[u] = *(const float4*)(Brow[u]);     pb1[u] = *(const float4*)(Brow[u] + 4);
    }

    #pragma unroll 1
    for (int kt = 0; kt < Cn / KC; kt++) {
        __syncthreads();                         // previous compute done reading smem
        #pragma unroll
        for (int u = 0; u < 3; u++) {
            uint4 va, vb;
            va.x = pk(pa0[u].x, pa0[u].y); va.y = pk(pa0[u].z, pa0[u].w);
            va.z = pk(pa1[u].x, pa1[u].y); va.w = pk(pa1[u].z, pa1[u].w);
            vb.x = pk(pb0[u].x, pb0[u].y); vb.y = pk(pb0[u].z, pb0[u].w);
            vb.z = pk(pb1[u].x, pb1[u].y); vb.w = pk(pb1[u].z, pb1[u].w);
            *(uint4*)(sA + rowL[u] * LDS_STRIDE + segL[u] * 8) = va;
            *(uint4*)(sB + rowL[u] * LDS_STRIDE + segL[u] * 8) = vb;
            if (doA) sqa[u] += pa0[u].x*pa0[u].x + pa0[u].y*pa0[u].y + pa0[u].z*pa0[u].z + pa0[u].w*pa0[u].w
                             + pa1[u].x*pa1[u].x + pa1[u].y*pa1[u].y + pa1[u].z*pa1[u].z + pa1[u].w*pa1[u].w;
            if (doB) sqb[u] += pb0[u].x*pb0[u].x + pb0[u].y*pb0[u].y + pb0[u].z*pb0[u].z + pb0[u].w*pb0[u].w
                             + pb1[u].x*pb1[u].x + pb1[u].y*pb1[u].y + pb1[u].z*pb1[u].z + pb1[u].w*pb1[u].w;
        }
        __syncthreads();
        if (kt < Cn / KC - 1) {                  // prefetch next chunk (latency hidden)
            const int k0 = (kt + 1) * KC;
            #pragma unroll
            for (int u = 0; u < 3; u++) {
                pa0[u] = *(const float4*)(Arow[u] + k0);     pa1[u] = *(const float4*)(Arow[u] + k0 + 4);
                pb0[u] = *(const float4*)(Brow[u] + k0);     pb1[u] = *(const float4*)(Brow[u] + k0 + 4);
            }
        }
        #pragma unroll
        for (int step = 0; step < KC / 16; step++) {
            uint32_t aF[3][4], bF[3][2];
            #pragma unroll
            for (int s = 0; s < 3; s++) ldm_x4(aF[s], aAddr[s] + step * 32);
            #pragma unroll
            for (int p = 0; p < 3; p++) ldm_x2(bF[p], bAddr[p] + step * 32);
            #pragma unroll
            for (int s = 0; s < 3; s++)
                #pragma unroll
                for (int p = 0; p < 3; p++) mma_bf16(acc[s][p], aF[s], bF[p]);
        }
    }

    if (doA) {
        #pragma unroll
        for (int u = 0; u < 3; u++) {
            float s = sqa[u];
            #pragma unroll
            for (int o = 1; o < 8; o <<= 1) s += __shfl_xor_sync(0xffffffffu, s, o);
            if ((lane & 7) == 0) g_anorm[b * NE + it * 96 + rowL[u]] = sqrtf(s);
        }
    }
    if (doB) {
        #pragma unroll
        for (int u = 0; u < 3; u++) {
            float s = sqb[u];
            #pragma unroll
            for (int o = 1; o < 8; o <<= 1) s += __shfl_xor_sync(0xffffffffu, s, o);
            if ((lane & 7) == 0) g_rnormO[b * NO + jt * 96 + rowL[u]] = 1.0f / sqrtf(s);
        }
    }

    float* sc = g_scores + ((size_t)b * NE + it * 96) * NO + jt * 96;
    const int tr = lane >> 2, tc = (lane & 3) * 2;
    #pragma unroll
    for (int s = 0; s < 3; s++) {
        #pragma unroll
        for (int p = 0; p < 3; p++) {
            const int r0 = wm * 48 + s * 16 + tr;
            const int c  = wn * 24 + p * 8 + tc;
            *(float2*)(sc + (size_t)r0 * NO + c)       = make_float2(acc[s][p][0], acc[s][p][1]);
            *(float2*)(sc + (size_t)(r0 + 8) * NO + c) = make_float2(acc[s][p][2], acc[s][p][3]);
        }
    }
}

// ---------------- K2: candidate filter + exact fp32 re-verify (R10 body + b0) ----------------
__device__ __forceinline__ float exact_score(const float4 a[8], const float* __restrict__ pb,
                                             int lane, float rn) {
    float s = 0.f;
    #pragma unroll
    for (int q = 0; q < 8; q++) {
        const float4 v = *(const float4*)(pb + q * 128 + lane * 4);
        s += a[q].x * v.x + a[q].y * v.y + a[q].z * v.z + a[q].w * v.w;
    }
    #pragma unroll
    for (int o = 16; o > 0; o >>= 1) s += __shfl_xor_sync(0xffffffffu, s, o);
    return s * rn;
}

__global__ __launch_bounds__(256) void k_filter_exact(const float* __restrict__ X, int b0) {
    const int w = threadIdx.x >> 5, lane = threadIdx.x & 31;
    const int b = blockIdx.x / 36 + b0, sub = blockIdx.x % 36;
    const int i = sub * 8 + w;
    const float* Xb = X + (size_t)b * Tn * Cn;

    const float* srow = g_scores + ((size_t)b * NE + i) * NO;
    const float* rnb  = g_rnormO + b * NO;
    float sc[9];
    #pragma unroll
    for (int q = 0; q < 9; q++) sc[q] = srow[q * 32 + lane] * rnb[q * 32 + lane];

    float m = sc[0];
    #pragma unroll
    for (int q = 1; q < 9; q++) m = fmaxf(m, sc[q]);
    #pragma unroll
    for (int o = 16; o > 0; o >>= 1) m = fmaxf(m, __shfl_xor_sync(0xffffffffu, m, o));
    const float thr = m - 0.012f * g_anorm[b * NE + i];   // 2B window, B=0.006|a| (bound 0.0041|a|)

    unsigned masks[9]; int tot = 0;
    #pragma unroll
    for (int q = 0; q < 9; q++) { masks[q] = __ballot_sync(0xffffffffu, sc[q] >= thr); tot += __popc(masks[q]); }

    if (tot == 1) {            // decided by the error bound alone
        if (lane == 0) {
            int bj = 0;
            #pragma unroll
            for (int q = 0; q < 9; q++) if (masks[q]) bj = q * 32 + __ffs(masks[q]) - 1;
            g_dst[b * NE + i] = bj;
        }
        return;
    }

    float4 a[8];
    const float* pa = Xb + (size_t)(2 * i + 2) * Cn;
    #pragma unroll
    for (int q = 0; q < 8; q++) a[q] = *(const float4*)(pa + q * 128 + lane * 4);

    float best = -3.0e38f; int bj = 0;
    #pragma unroll 1
    for (int q = 0; q < 9; q++) {                 // ascending q, ascending bit => ascending j
        unsigned mask = masks[q];
        while (mask) {
            const int bit = __ffs(mask) - 1;
            mask &= mask - 1;
            const int j = q * 32 + bit;
            const float v = exact_score(a, Xb + (size_t)(2 * j + 1) * Cn, lane, rnb[j]);
            if (v > best) { best = v; bj = j; }   // strict '>' keeps lowest j on tie
        }
    }
    if (lane == 0) g_dst[b * NE + i] = bj;
}

// ---------------- K3: deterministic CSR build (parallel prefix, no atomics) ----------------
__global__ __launch_bounds__(288) void k_build_csr(int b0) {
    __shared__ int s_dst[NE];
    __shared__ int s_ws[9];
    const int b = blockIdx.x + b0, t = threadIdx.x, wid = t >> 5, lane = t & 31;
    s_dst[t] = g_dst[b * NE + t];
    __syncthreads();

    int c = 0;
    #pragma unroll 4
    for (int i = 0; i < NE; i++) c += (s_dst[i] == t);

    int inc = c;
    #pragma unroll
    for (int o = 1; o < 32; o <<= 1) {
        const int v = __shfl_up_sync(0xffffffffu, inc, o);
        if (lane >= o) inc += v;
    }
    if (lane == 31) s_ws[wid] = inc;
    __syncthreads();
    int wo = 0;
    #pragma unroll
    for (int wv = 0; wv < 9; wv++) wo += (wv < wid) ? s_ws[wv] : 0;
    const int off = wo + inc - c;   // exclusive prefix

    int wv = 0;
    for (int i = 0; i < NE; i++)
        if (s_dst[i] == t) g_list[b * NE + off + (wv++)] = i;   // ascending i
    g_off[b * NO + t] = off;
    g_cnt[b * NO + t] = c;
}

// ---------------- K4: merge via CSR gather (R10 body + b0) ----------------
__global__ __launch_bounds__(256) void k_merge(const float* __restrict__ X, float* __restrict__ out, int b0) {
    const int b = blockIdx.y + b0, row = blockIdx.x, t = threadIdx.x;
    float* orow = out + ((size_t)b * TOUT + row) * Cn;
    const float* Xb = X + (size_t)b * Tn * Cn;

    if (row == 0) {   // lone unm token = original token 0
        *(float4*)(orow + t * 4) = *(const float4*)(Xb + t * 4);
        return;
    }
    const int j   = row - 1;
    const int off = g_off[b * NO + j];
    const int cnt = g_cnt[b * NO + j];

    float4 a = *(const float4*)(Xb + (size_t)(2 * j + 1) * Cn + t * 4);
    for (int s = 0; s < cnt; s++) {
        const int i = g_list[b * NE + off + s];               // ascending i -> fixed fp order
        const float4 v = *(const float4*)(Xb + (size_t)(2 * (i + 1)) * Cn + t * 4);
        a.x += v.x; a.y += v.y; a.z += v.z; a.w += v.w;
    }
    const float inv = 1.0f / (float)(cnt + 1);
    a.x *= inv; a.y *= inv; a.z *= inv; a.w *= inv;
    *(float4*)(orow + t * 4) = a;
}

// ---------------- launch: 2-chunk two-stream pipeline (32 batches/chunk) ----------------
// Chunk granularity chosen so every launch is >= ~2 full waves (R12's 4x16 chunking
// under-filled the chip). Capture-safe event fork/join, as validated in R12.
extern "C" void kernel_launch(void* const* d_in, const int* in_sizes, int n_in,
                              void* d_out, int out_size) {
    const float* X = (const float*)d_in[0];
    float* out = (float*)d_out;

    static cudaStream_t s2 = nullptr;
    static cudaEvent_t evG[2], evJ;
    if (!s2) {
        cudaStreamCreateWithFlags(&s2, cudaStreamNonBlocking);
        for (int c = 0; c < 2; c++) cudaEventCreateWithFlags(&evG[c], cudaEventDisableTiming);
        cudaEventCreateWithFlags(&evJ, cudaEventDisableTiming);
    }

    for (int c = 0; c < 2; c++) {
        const int b0 = c * BCHUNK;
        k_gemm<<<dim3(3, 3, BCHUNK), 256>>>(X, b0);
        cudaEventRecord(evG[c], 0);                       // fork point on capture stream
        cudaStreamWaitEvent(s2, evG[c], 0);
        k_filter_exact<<<BCHUNK * 36, 256, 0, s2>>>(X, b0);
        k_build_csr   <<<BCHUNK, 288, 0, s2>>>(b0);
        k_merge       <<<dim3(TOUT, BCHUNK), 256, 0, s2>>>(X, out, b0);
    }
    cudaEventRecord(evJ, s2);                             // join s2 back
    cudaStreamWaitEvent(0, evJ, 0);
}